// round 2
// baseline (speedup 1.0000x reference)
#include <cuda_runtime.h>
#include <cfloat>
#include <cstdint>

#define D       64
#define BLOCK   256
#define KCODES  512
#define MARGIN  1e-4f

__device__ float g_partials[8192];

// smem: codebook [KCODES*D] + c2 (ref-emulated) [KCODES] + best ids [BLOCK] + warp partials [8]
#define SMEM_FLOATS (KCODES * D + KCODES + BLOCK + 8)

#define MUL_F32X2(out, a, b) \
    asm("mul.rn.f32x2 %0, %1, %2;" : "=l"(out) : "l"(a), "l"(b))
#define ADD_F32X2(out, a, b) \
    asm("add.rn.f32x2 %0, %1, %2;" : "=l"(out) : "l"(a), "l"(b))

// Emulate XLA-GPU warp row-reduction order for sum over 64 elems of squares:
// leaf_t = fl(fl(x_t^2) + fl(x_{t+32}^2)), t=0..31; then shfl-down tree 16,8,4,2,1.
__device__ __forceinline__ float emul_sumsq_scalar(const float* __restrict__ x)
{
    float leaf[32];
    #pragma unroll
    for (int t = 0; t < 32; t++)
        leaf[t] = __fadd_rn(__fmul_rn(x[t], x[t]), __fmul_rn(x[t+32], x[t+32]));
    #pragma unroll
    for (int off = 16; off >= 1; off >>= 1)
        #pragma unroll
        for (int t = 0; t < 16; t++)
            if (t < off) leaf[t] = __fadd_rn(leaf[t], leaf[t + off]);
    return leaf[0];
}

// Exact emulation of reference score: w = fl( fl(A - fl(2*dot)) + C2 ),
// dot = ascending-k sequential fmaf (cuBLAS SGEMM accumulation order).
__device__ __forceinline__ float emul_score(
    const unsigned long long* __restrict__ za, const float* __restrict__ c,
    float A, float C2)
{
    float acc = 0.f;
    #pragma unroll
    for (int i = 0; i < D / 2; i++) {
        float lo, hi;
        asm("mov.b64 {%0, %1}, %2;" : "=f"(lo), "=f"(hi) : "l"(za[i]));
        acc = __fmaf_rn(lo, c[2*i + 0], acc);
        acc = __fmaf_rn(hi, c[2*i + 1], acc);
    }
    float v = __fsub_rn(A, __fmul_rn(2.0f, acc));
    return __fadd_rn(v, C2);
}

__global__ void __launch_bounds__(BLOCK, 1) vq_kernel(
    const float* __restrict__ z, const float* __restrict__ cb,
    float* __restrict__ out, int N)
{
    extern __shared__ float smem[];
    float* s_cb   = smem;                           // KCODES * D
    float* s_c2   = smem + KCODES * D;              // KCODES (ref-order emulated)
    int*   s_best = (int*)(s_c2 + KCODES);          // BLOCK
    float* s_red  = (float*)(s_best + BLOCK);       // 8

    const int tid = threadIdx.x;

    // ---- cooperative codebook load ----
    {
        const float4* src = (const float4*)cb;
        float4* dst = (float4*)s_cb;
        #pragma unroll
        for (int i = 0; i < (KCODES * D / 4) / BLOCK; i++)
            dst[i * BLOCK + tid] = src[i * BLOCK + tid];
    }
    __syncthreads();

    // ---- C2_k with reference reduce-order emulation ----
    #pragma unroll
    for (int k = tid; k < KCODES; k += BLOCK)
        s_c2[k] = emul_sumsq_scalar(s_cb + k * D);
    __syncthreads();

    const int row = blockIdx.x * BLOCK + tid;

    // ---- load z row: 32 packed f32x2 pairs ----
    unsigned long long za[D / 2];
    {
        const float4* zp = (const float4*)(z + (size_t)row * D);
        #pragma unroll
        for (int i = 0; i < D / 4; i++) {
            float4 v = zp[i];
            asm("mov.b64 %0, {%1, %2};" : "=l"(za[2*i+0]) : "f"(v.x), "f"(v.y));
            asm("mov.b64 %0, {%1, %2};" : "=l"(za[2*i+1]) : "f"(v.z), "f"(v.w));
        }
    }

    // ---- A = sum z^2 in emulated reference order (packed tree) ----
    float A;
    {
        unsigned long long sq[32];
        #pragma unroll
        for (int j = 0; j < 32; j++) MUL_F32X2(sq[j], za[j], za[j]);
        unsigned long long pl[16];
        #pragma unroll
        for (int j = 0; j < 16; j++) ADD_F32X2(pl[j], sq[j], sq[j + 16]); // leaf_t = sq_t + sq_{t+32}
        #pragma unroll
        for (int j = 0; j < 8; j++)  ADD_F32X2(pl[j], pl[j], pl[j + 8]); // off 16
        #pragma unroll
        for (int j = 0; j < 4; j++)  ADD_F32X2(pl[j], pl[j], pl[j + 4]); // off 8
        #pragma unroll
        for (int j = 0; j < 2; j++)  ADD_F32X2(pl[j], pl[j], pl[j + 2]); // off 4
        ADD_F32X2(pl[0], pl[0], pl[1]);                                  // off 2
        float a0, a1;
        asm("mov.b64 {%0, %1}, %2;" : "=f"(a0), "=f"(a1) : "l"(pl[0]));
        A = __fadd_rn(a0, a1);                                           // off 1
    }

    // ---- coarse pass: packed-FFMA2 scores, track top-3 (value,index) ----
    float m1 = FLT_MAX, m2 = FLT_MAX, m3 = FLT_MAX;
    int   k1 = 0, k2 = 0, k3 = 0;
    #pragma unroll 2
    for (int k = 0; k < KCODES; k++) {
        unsigned long long a0 = 0ull, a1 = 0ull;
        const float4* c4 = (const float4*)(s_cb + k * D);
        #pragma unroll
        for (int i = 0; i < D / 4; i++) {
            float4 cv = c4[i];
            asm("{ .reg .b64 p; mov.b64 p, {%1, %2}; fma.rn.f32x2 %0, %3, p, %0; }"
                : "+l"(a0) : "f"(cv.x), "f"(cv.y), "l"(za[2*i+0]));
            asm("{ .reg .b64 p; mov.b64 p, {%1, %2}; fma.rn.f32x2 %0, %3, p, %0; }"
                : "+l"(a1) : "f"(cv.z), "f"(cv.w), "l"(za[2*i+1]));
        }
        float l0, h0, l1, h1;
        asm("mov.b64 {%0, %1}, %2;" : "=f"(l0), "=f"(h0) : "l"(a0));
        asm("mov.b64 {%0, %1}, %2;" : "=f"(l1), "=f"(h1) : "l"(a1));
        float dot = (l0 + h0) + (l1 + h1);
        float s = fmaf(-2.0f, dot, s_c2[k]);
        if (s < m1)      { m3 = m2; k3 = k2; m2 = m1; k2 = k1; m1 = s; k1 = k; }
        else if (s < m2) { m3 = m2; k3 = k2; m2 = s; k2 = k; }
        else if (s < m3) { m3 = s; k3 = k; }
    }

    // ---- exact-emulation rescue on candidates ----
    int   bestk;
    float w_best;
    if (m3 < m1 + MARGIN) {
        // rare fallback: fully exact scan, first-min wins
        bestk = 0; w_best = FLT_MAX;
        for (int k = 0; k < KCODES; k++) {
            float w = emul_score(za, s_cb + k * D, A, s_c2[k]);
            if (w < w_best) { w_best = w; bestk = k; }
        }
    } else {
        int ncand = (m2 < m1 + MARGIN) ? 2 : 1;
        int ca = k1, cb_ = k2;
        if (ncand == 2 && cb_ < ca) { int t = ca; ca = cb_; cb_ = t; }
        w_best = emul_score(za, s_cb + ca * D, A, s_c2[ca]);
        bestk = ca;
        if (ncand == 2) {
            float w2 = emul_score(za, s_cb + cb_ * D, A, s_c2[cb_]);
            if (w2 < w_best) { w_best = w2; bestk = cb_; }   // strict <: lower index wins ties
        }
    }

    s_best[tid] = bestk;

    // ---- loss partial: ||z - c_best||^2 = A - 2*dot + C2 = w_best ----
    float sq = w_best;
    #pragma unroll
    for (int off = 16; off; off >>= 1)
        sq += __shfl_down_sync(0xFFFFFFFFu, sq, off);
    if ((tid & 31) == 0) s_red[tid >> 5] = sq;
    __syncthreads();
    if (tid == 0) {
        float t = 0.f;
        #pragma unroll
        for (int w = 0; w < BLOCK / 32; w++) t += s_red[w];
        g_partials[blockIdx.x] = t;
    }

    // ---- ids (float) ----
    float* ids_out = out + (size_t)N * D + 1;
    ids_out[row] = (float)bestk;

    // ---- q_ste = fl(z + fl(q - z)), emulated, coalesced float4 ----
    {
        const size_t base4 = (size_t)blockIdx.x * BLOCK * (D / 4);
        const float4* z4g = (const float4*)z + base4;
        float4* q4 = (float4*)out + base4;
        #pragma unroll
        for (int it = 0; it < (BLOCK * (D / 4)) / BLOCK; it++) {
            int f  = it * BLOCK + tid;
            int r  = f >> 4;
            int d4 = f & 15;
            int bk = s_best[r];
            float4 c  = ((const float4*)(s_cb + bk * D))[d4];
            float4 zv = z4g[f];
            float4 o;
            o.x = __fadd_rn(zv.x, __fsub_rn(c.x, zv.x));
            o.y = __fadd_rn(zv.y, __fsub_rn(c.y, zv.y));
            o.z = __fadd_rn(zv.z, __fsub_rn(c.z, zv.z));
            o.w = __fadd_rn(zv.w, __fsub_rn(c.w, zv.w));
            q4[f] = o;
        }
    }
}

__global__ void vq_reduce(float* __restrict__ out, int nblocks, int N)
{
    __shared__ float s[BLOCK];
    float v = 0.f;
    for (int i = threadIdx.x; i < nblocks; i += BLOCK)
        v += g_partials[i];
    s[threadIdx.x] = v;
    __syncthreads();
    #pragma unroll
    for (int off = BLOCK / 2; off; off >>= 1) {
        if (threadIdx.x < off) s[threadIdx.x] += s[threadIdx.x + off];
        __syncthreads();
    }
    if (threadIdx.x == 0) {
        float mean = s[0] / (float)((size_t)N * D);
        out[(size_t)N * D] = mean + 0.25f * mean;   // mse + commit_weight * mse
    }
}

extern "C" void kernel_launch(void* const* d_in, const int* in_sizes, int n_in,
                              void* d_out, int out_size)
{
    const float* z  = (const float*)d_in[0];
    const float* cb = (const float*)d_in[1];
    float* out = (float*)d_out;

    const int N = in_sizes[0] / D;           // 262144
    const int nblocks = (N + BLOCK - 1) / BLOCK;

    const size_t smem_bytes = SMEM_FLOATS * sizeof(float);
    cudaFuncSetAttribute(vq_kernel, cudaFuncAttributeMaxDynamicSharedMemorySize,
                         (int)smem_bytes);

    vq_kernel<<<nblocks, BLOCK, smem_bytes>>>(z, cb, out, N);
    vq_reduce<<<1, BLOCK>>>(out, nblocks, N);
}